// round 12
// baseline (speedup 1.0000x reference)
#include <cuda_runtime.h>
#include <cuda_bf16.h>
#include <cstddef>
#include <cstdint>

#define BATCH 2
#define NPTS  8192
#define DIM   64
#define KNN   16
#define NPOINTS_TOTAL (BATCH * NPTS)
#define PPB   8    // points per attn block (128 rows)

// tf32 operand rounding for the K=64 GEMMs (cublas tf32 path emulation).
__device__ __forceinline__ float tf32r(float x) {
    uint32_t y;
    asm("cvt.rna.tf32.f32 %0, %1;" : "=r"(y) : "f"(x));
    return __uint_as_float(y);
}

// ---- packed fp32x2 helpers (Blackwell dual-fp32 pipe) ----
__device__ __forceinline__ unsigned long long pk2(float lo, float hi) {
    unsigned long long r;
    asm("mov.b64 %0, {%1, %2};" : "=l"(r) : "f"(lo), "f"(hi));
    return r;
}
__device__ __forceinline__ unsigned long long splat2(float v) {
    unsigned long long r;
    asm("mov.b64 %0, {%1, %1};" : "=l"(r) : "f"(v));
    return r;
}
__device__ __forceinline__ void fma2(unsigned long long& d,
                                     unsigned long long a, unsigned long long b) {
    asm("fma.rn.f32x2 %0, %1, %2, %0;" : "+l"(d) : "l"(a), "l"(b));
}
__device__ __forceinline__ void unpk2(unsigned long long v, float& lo, float& hi) {
    asm("mov.b64 {%0, %1}, %2;" : "=f"(lo), "=f"(hi) : "l"(v));
}

// ---------------- scratch (static device globals; no runtime allocation) ----
__device__ float g_xq[NPOINTS_TOTAL * DIM];
__device__ float g_xk[NPOINTS_TOTAL * DIM];
__device__ float g_xv[NPOINTS_TOTAL * DIM];
__device__ int   g_idx[NPOINTS_TOTAL * KNN];

// ============================================================================
// KNN kernel v5: warp-collective top-16, FOUR queries per warp.
// Each candidate float4 is read once from smem and scored against 4 queries:
// LDS bytes/pair 16B -> 4B. Distance arithmetic, (d2, idx) tie semantics and
// the insert machinery are identical to passing R9 (selected sets unchanged).
// ============================================================================
__global__ void __launch_bounds__(256) knn_kernel(const float* __restrict__ pos) {
    const int b    = blockIdx.x >> 8;      // 256 blocks per batch
    const int blk  = blockIdx.x & 255;
    const int wid  = threadIdx.x >> 5;
    const int lane = threadIdx.x & 31;
    const int q0   = blk * 32 + wid * 4;   // first of this warp's 4 queries
    const unsigned FULL = 0xffffffffu;

    const float* posb = pos + (size_t)b * NPTS * 3;
    __shared__ float4 tile[1024];

    float qx[4], qy[4], qz[4], sqq[4];
#pragma unroll
    for (int i = 0; i < 4; i++) {
        qx[i] = posb[(q0 + i) * 3 + 0];
        qy[i] = posb[(q0 + i) * 3 + 1];
        qz[i] = posb[(q0 + i) * 3 + 2];
        sqq[i] = __fadd_rn(__fadd_rn(__fmul_rn(qx[i], qx[i]), __fmul_rn(qy[i], qy[i])),
                           __fmul_rn(qz[i], qz[i]));
    }

    float kd[4];  int ki[4];
    float thr[4]; int thrid[4];
#pragma unroll
    for (int i = 0; i < 4; i++) {
        kd[i] = 1e30f; ki[i] = 0x7fffffff;
        thr[i] = 1e30f; thrid[i] = 0x7fffffff;
    }

    for (int base = 0; base < NPTS; base += 1024) {
        __syncthreads();
        for (int t = threadIdx.x; t < 1024; t += 256) {
            const int j = base + t;
            const float px = posb[j * 3 + 0];
            const float py = posb[j * 3 + 1];
            const float pz = posb[j * 3 + 2];
            const float sq = __fadd_rn(__fadd_rn(__fmul_rn(px, px), __fmul_rn(py, py)),
                                       __fmul_rn(pz, pz));
            tile[t] = make_float4(px, py, pz, sq);
        }
        __syncthreads();

#pragma unroll 2
        for (int it = 0; it < 32; it++) {
            const int t = it * 32 + lane;
            const float4 p = tile[t];
            const int   j = base + t;
            float d2[4];
            bool  qual[4];
            bool  any = false;
#pragma unroll
            for (int i = 0; i < 4; i++) {
                const float dot = __fadd_rn(__fadd_rn(__fmul_rn(qx[i], p.x),
                                                      __fmul_rn(qy[i], p.y)),
                                            __fmul_rn(qz[i], p.z));
                d2[i] = __fsub_rn(__fadd_rn(sqq[i], p.w), __fmul_rn(2.0f, dot));
                qual[i] = (d2[i] < thr[i]) || (d2[i] == thr[i] && j < thrid[i]);
                any |= qual[i];
            }
            if (__ballot_sync(FULL, any)) {
#pragma unroll
                for (int i = 0; i < 4; i++) {
                    unsigned mask = __ballot_sync(FULL, qual[i]);
                    while (mask) {
                        const int src = __ffs(mask) - 1;
                        mask &= mask - 1;
                        const float nd = __shfl_sync(FULL, d2[i], src);
                        const int   nj = __shfl_sync(FULL, j, src);
                        if (nd < thr[i] || (nd == thr[i] && nj < thrid[i])) {
                            const bool less = (kd[i] < nd) || (kd[i] == nd && ki[i] < nj);
                            const unsigned lm = __ballot_sync(FULL, less && (lane < 16));
                            const int pos2 = __popc(lm);
                            const float upkd = __shfl_up_sync(FULL, kd[i], 1);
                            const int   upki = __shfl_up_sync(FULL, ki[i], 1);
                            if (lane >= pos2) {
                                if (lane == pos2) { kd[i] = nd; ki[i] = nj; }
                                else              { kd[i] = upkd; ki[i] = upki; }
                            }
                            thr[i]   = __shfl_sync(FULL, kd[i], 15);
                            thrid[i] = __shfl_sync(FULL, ki[i], 15);
                        }
                    }
                }
            }
        }
    }

#pragma unroll
    for (int i = 0; i < 4; i++)
        if (lane < 16) g_idx[((b << 13) + q0 + i) * KNN + lane] = ki[i];
}

// ============================================================================
// Projection kernel (unchanged from passing R9).
// ============================================================================
struct ProjSmem {
    float WqT[64 * 68];
    float WkT[64 * 68];
    float WvT[64 * 68];
    float xs[16 * 68];
};

__global__ void __launch_bounds__(1024) proj_kernel(const float* __restrict__ x,
                                                    const float* __restrict__ Wq,
                                                    const float* __restrict__ Wk,
                                                    const float* __restrict__ Wv) {
    extern __shared__ __align__(16) unsigned char proj_raw[];
    ProjSmem* S = reinterpret_cast<ProjSmem*>(proj_raw);

    const int tid = threadIdx.x;
    const int r = tid >> 6;
    const int d = tid & 63;

    for (int e = tid; e < 4096; e += 1024) {
        const int i = e >> 6, c = e & 63;
        S->WqT[c * 68 + i] = tf32r(Wq[e]);
        S->WkT[c * 68 + i] = tf32r(Wk[e]);
        S->WvT[c * 68 + i] = tf32r(Wv[e]);
    }
    const size_t rowbase = (size_t)blockIdx.x * 16;
    for (int e = tid; e < 16 * 64; e += 1024) {
        const int rr = e >> 6, c = e & 63;
        S->xs[rr * 68 + c] = tf32r(x[(rowbase + rr) * 64 + c]);
    }
    __syncthreads();

    const float4* xv4 = (const float4*)(S->xs + r * 68);
    const float4* wq4 = (const float4*)(S->WqT + d * 68);
    const float4* wk4 = (const float4*)(S->WkT + d * 68);
    const float4* wv4 = (const float4*)(S->WvT + d * 68);
    float aq = 0.f, ak = 0.f, av = 0.f;
#pragma unroll
    for (int i = 0; i < 16; i++) {
        const float4 xv = xv4[i];
        const float4 wq = wq4[i];
        const float4 wk = wk4[i];
        const float4 wv = wv4[i];
        aq = fmaf(wq.x, xv.x, aq); aq = fmaf(wq.y, xv.y, aq);
        aq = fmaf(wq.z, xv.z, aq); aq = fmaf(wq.w, xv.w, aq);
        ak = fmaf(wk.x, xv.x, ak); ak = fmaf(wk.y, xv.y, ak);
        ak = fmaf(wk.z, xv.z, ak); ak = fmaf(wk.w, xv.w, ak);
        av = fmaf(wv.x, xv.x, av); av = fmaf(wv.y, xv.y, av);
        av = fmaf(wv.z, xv.z, av); av = fmaf(wv.w, xv.w, av);
    }
    const size_t o = (rowbase + r) * 64 + d;
    g_xq[o] = aq; g_xk[o] = ak; g_xv[o] = av;
}

// ============================================================================
// Attention kernel v4 (unchanged from passing R9): fp32x2 register-blocked GEMM.
// ============================================================================
struct AttnSmem {
    float actA[128 * 68];
    float actB[128 * 68];
    float wbuf[64 * 68];
    float qs[PPB * 68];
    float agg[PPB * 68];
    float rel[128 * 4];
    float P1s[3 * 64];
    float pb1s[64], pb2s[64], ab1s[64], ab2s[64], bfs[64];
};

__device__ __forceinline__ void stage_w(float* __restrict__ dst,
                                        const float* __restrict__ W, int tid) {
    for (int e = tid; e < 4096; e += 256)
        dst[(e >> 6) * 68 + (e & 63)] = tf32r(W[e]);
}

__global__ void __launch_bounds__(256, 2) attn_kernel(
    const float* __restrict__ x,
    const float* __restrict__ pos,
    const float* __restrict__ P1,
    const float* __restrict__ pb1,
    const float* __restrict__ P2,
    const float* __restrict__ pb2,
    const float* __restrict__ A1,
    const float* __restrict__ ab1,
    const float* __restrict__ A2,
    const float* __restrict__ ab2,
    const float* __restrict__ Wf,
    const float* __restrict__ bf,
    float* __restrict__ out) {
    extern __shared__ __align__(16) unsigned char attn_raw[];
    AttnSmem* S = reinterpret_cast<AttnSmem*>(attn_raw);

    const int tid = threadIdx.x;
    const int tx  = tid & 15;
    const int ty  = tid >> 4;
    const int n0  = tx * 4;
    const int m0  = ty * 8;
    const int p   = ty >> 1;
    const int pbase = blockIdx.x * PPB;
    const int b   = pbase >> 13;

    if (tid < 192) S->P1s[tid] = P1[tid];
    if (tid < 64) {
        S->pb1s[tid] = pb1[tid];
        S->pb2s[tid] = pb2[tid];
        S->ab1s[tid] = ab1[tid];
        S->ab2s[tid] = ab2[tid];
        S->bfs[tid]  = bf[tid];
    }
    for (int e = tid; e < PPB * 64; e += 256)
        S->qs[(e >> 6) * 68 + (e & 63)] = g_xq[(size_t)pbase * 64 + e];

    int grow[8];
#pragma unroll
    for (int r = 0; r < 8; r++)
        grow[r] = (b << 13) + g_idx[pbase * KNN + m0 + r];

    for (int e = tid; e < 128 * 3; e += 256) {
        const int m = e / 3, c = e % 3;
        const int pp = m >> 4;
        const int nb = g_idx[pbase * KNN + m];
        S->rel[m * 4 + c] = pos[(size_t)(pbase + pp) * 3 + c]
                          - pos[((size_t)(b << 13) + nb) * 3 + c];
    }
    stage_w(S->wbuf, P2, tid);
    __syncthreads();

    {
        float4* a4 = (float4*)(S->actA);
#pragma unroll
        for (int r = 0; r < 8; r++) {
            const int m = m0 + r;
            const float r0 = S->rel[m * 4 + 0];
            const float r1 = S->rel[m * 4 + 1];
            const float r2 = S->rel[m * 4 + 2];
            float4 hv;
#pragma unroll
            for (int c = 0; c < 4; c++) {
                const int n = n0 + c;
                const float dotp = __fadd_rn(__fadd_rn(__fmul_rn(r0, S->P1s[n]),
                                                       __fmul_rn(r1, S->P1s[64 + n])),
                                             __fmul_rn(r2, S->P1s[128 + n]));
                const float hd = __fadd_rn(dotp, S->pb1s[n]);
                ((float*)&hv)[c] = tf32r(fmaxf(hd, 0.f));
            }
            a4[m * 17 + tx] = hv;
        }
    }
    __syncthreads();

    unsigned long long acc2[8][2];
    float pe[8][4];
    const ulonglong2* wb2 = (const ulonglong2*)(S->wbuf);

#define ACC_INIT(BIAS)                                                        \
    {                                                                         \
        const unsigned long long b01 = pk2((BIAS)[n0 + 0], (BIAS)[n0 + 1]);   \
        const unsigned long long b23 = pk2((BIAS)[n0 + 2], (BIAS)[n0 + 3]);   \
        _Pragma("unroll")                                                     \
        for (int r = 0; r < 8; r++) { acc2[r][0] = b01; acc2[r][1] = b23; }   \
    }

#define GEMM_PHASE(INBUF)                                                     \
    {                                                                         \
        const float4* in4 = (const float4*)(INBUF);                           \
        _Pragma("unroll 2")                                                   \
        for (int kq = 0; kq < 16; kq++) {                                     \
            const ulonglong2 W0 = wb2[(4 * kq + 0) * 17 + tx];                \
            const ulonglong2 W1 = wb2[(4 * kq + 1) * 17 + tx];                \
            const ulonglong2 W2 = wb2[(4 * kq + 2) * 17 + tx];                \
            const ulonglong2 W3 = wb2[(4 * kq + 3) * 17 + tx];                \
            _Pragma("unroll")                                                 \
            for (int r = 0; r < 8; r++) {                                     \
                const float4 a = in4[(m0 + r) * 17 + kq];                     \
                const unsigned long long ax = splat2(a.x);                    \
                const unsigned long long ay = splat2(a.y);                    \
                const unsigned long long az = splat2(a.z);                    \
                const unsigned long long aw = splat2(a.w);                    \
                fma2(acc2[r][0], ax, W0.x); fma2(acc2[r][1], ax, W0.y);       \
                fma2(acc2[r][0], ay, W1.x); fma2(acc2[r][1], ay, W1.y);       \
                fma2(acc2[r][0], az, W2.x); fma2(acc2[r][1], az, W2.y);       \
                fma2(acc2[r][0], aw, W3.x); fma2(acc2[r][1], aw, W3.y);       \
            }                                                                 \
        }                                                                     \
    }

    ACC_INIT(S->pb2s);
    GEMM_PHASE(S->actA);
    {
        const float4 qv = ((const float4*)(S->qs))[p * 17 + tx];
        float4* b4 = (float4*)(S->actB);
#pragma unroll
        for (int r = 0; r < 8; r++) {
            unpk2(acc2[r][0], pe[r][0], pe[r][1]);
            unpk2(acc2[r][1], pe[r][2], pe[r][3]);
            const float4 kv = *(const float4*)(g_xk + (size_t)grow[r] * 64 + n0);
            float4 hv;
            hv.x = tf32r(qv.x - kv.x + pe[r][0]);
            hv.y = tf32r(qv.y - kv.y + pe[r][1]);
            hv.z = tf32r(qv.z - kv.z + pe[r][2]);
            hv.w = tf32r(qv.w - kv.w + pe[r][3]);
            b4[(m0 + r) * 17 + tx] = hv;
        }
    }
    __syncthreads();
    stage_w(S->wbuf, A1, tid);
    __syncthreads();

    ACC_INIT(S->ab1s);
    GEMM_PHASE(S->actB);
    {
        float4* a4 = (float4*)(S->actA);
#pragma unroll
        for (int r = 0; r < 8; r++) {
            float t0, t1, t2, t3;
            unpk2(acc2[r][0], t0, t1);
            unpk2(acc2[r][1], t2, t3);
            float4 tv;
            tv.x = tf32r(fmaxf(t0, 0.f));
            tv.y = tf32r(fmaxf(t1, 0.f));
            tv.z = tf32r(fmaxf(t2, 0.f));
            tv.w = tf32r(fmaxf(t3, 0.f));
            a4[(m0 + r) * 17 + tx] = tv;
        }
    }
    __syncthreads();
    stage_w(S->wbuf, A2, tid);
    __syncthreads();

    ACC_INIT(S->ab2s);
    GEMM_PHASE(S->actA);
    {
        float acc[8][4];
#pragma unroll
        for (int r = 0; r < 8; r++) {
            unpk2(acc2[r][0], acc[r][0], acc[r][1]);
            unpk2(acc2[r][1], acc[r][2], acc[r][3]);
        }
        float ev[8][4];
#pragma unroll
        for (int c = 0; c < 4; c++) {
            float m = acc[0][c];
#pragma unroll
            for (int r = 1; r < 8; r++) m = fmaxf(m, acc[r][c]);
            const float om = __shfl_xor_sync(0xffffffffu, m, 16);
            m = fmaxf(m, om);
            float s = 0.f;
#pragma unroll
            for (int r = 0; r < 8; r++) {
                ev[r][c] = __expf((acc[r][c] - m) * 0.125f);
                s += ev[r][c];
            }
            s += __shfl_xor_sync(0xffffffffu, s, 16);
#pragma unroll
            for (int r = 0; r < 8; r++) ev[r][c] /= s;
        }
        float ag[4] = {0.f, 0.f, 0.f, 0.f};
#pragma unroll
        for (int r = 0; r < 8; r++) {
            const float4 vv = *(const float4*)(g_xv + (size_t)grow[r] * 64 + n0);
            ag[0] += ev[r][0] * (vv.x + pe[r][0]);
            ag[1] += ev[r][1] * (vv.y + pe[r][1]);
            ag[2] += ev[r][2] * (vv.z + pe[r][2]);
            ag[3] += ev[r][3] * (vv.w + pe[r][3]);
        }
#pragma unroll
        for (int c = 0; c < 4; c++)
            ag[c] += __shfl_xor_sync(0xffffffffu, ag[c], 16);
        if ((ty & 1) == 0) {
            float4 av;
            av.x = tf32r(ag[0]); av.y = tf32r(ag[1]);
            av.z = tf32r(ag[2]); av.w = tf32r(ag[3]);
            ((float4*)(S->agg))[p * 17 + tx] = av;
        }
    }
    __syncthreads();
    stage_w(S->wbuf, Wf, tid);
    __syncthreads();

#pragma unroll
    for (int t2 = 0; t2 < 2; t2++) {
        const int oi = tid + 256 * t2;
        const int pp = oi >> 6;
        const int n  = oi & 63;
        float o = S->bfs[n] + x[(size_t)(pbase + pp) * 64 + n];
        const float* ar = S->agg + pp * 68;
#pragma unroll
        for (int k = 0; k < 64; k++)
            o = fmaf(ar[k], S->wbuf[k * 68 + n], o);
        out[(size_t)(pbase + pp) * 64 + n] = o;
    }
#undef GEMM_PHASE
#undef ACC_INIT
}

// ============================================================================
// launch
// ============================================================================
extern "C" void kernel_launch(void* const* d_in, const int* in_sizes, int n_in,
                              void* d_out, int out_size) {
    const float* x   = (const float*)d_in[0];
    const float* pos = (const float*)d_in[1];
    const float* Wq  = (const float*)d_in[2];
    const float* Wk  = (const float*)d_in[3];
    const float* Wv  = (const float*)d_in[4];
    const float* P1  = (const float*)d_in[5];
    const float* pb1 = (const float*)d_in[6];
    const float* P2  = (const float*)d_in[7];
    const float* pb2 = (const float*)d_in[8];
    const float* A1  = (const float*)d_in[9];
    const float* ab1 = (const float*)d_in[10];
    const float* A2  = (const float*)d_in[11];
    const float* ab2 = (const float*)d_in[12];
    const float* Wf  = (const float*)d_in[13];
    const float* bf  = (const float*)d_in[14];
    float* out = (float*)d_out;

    cudaFuncSetAttribute(proj_kernel, cudaFuncAttributeMaxDynamicSharedMemorySize,
                         (int)sizeof(ProjSmem));
    cudaFuncSetAttribute(attn_kernel, cudaFuncAttributeMaxDynamicSharedMemorySize,
                         (int)sizeof(AttnSmem));

    knn_kernel<<<512, 256>>>(pos);
    proj_kernel<<<1024, 1024, sizeof(ProjSmem)>>>(x, Wq, Wk, Wv);
    attn_kernel<<<NPOINTS_TOTAL / PPB, 256, sizeof(AttnSmem)>>>(
        x, pos, P1, pb1, P2, pb2, A1, ab1, A2, ab2, Wf, bf, out);
}

// round 13
// speedup vs baseline: 1.2429x; 1.2429x over previous
#include <cuda_runtime.h>
#include <cuda_bf16.h>
#include <cstddef>
#include <cstdint>

#define BATCH 2
#define NPTS  8192
#define DIM   64
#define KNN   16
#define NPOINTS_TOTAL (BATCH * NPTS)
#define PPB   8    // points per attn block (128 rows)

// tf32 operand rounding for the K=64 GEMMs (cublas tf32 path emulation).
__device__ __forceinline__ float tf32r(float x) {
    uint32_t y;
    asm("cvt.rna.tf32.f32 %0, %1;" : "=r"(y) : "f"(x));
    return __uint_as_float(y);
}

// ---- packed fp32x2 helpers (Blackwell dual-fp32 pipe) ----
__device__ __forceinline__ unsigned long long pk2(float lo, float hi) {
    unsigned long long r;
    asm("mov.b64 %0, {%1, %2};" : "=l"(r) : "f"(lo), "f"(hi));
    return r;
}
__device__ __forceinline__ unsigned long long splat2(float v) {
    unsigned long long r;
    asm("mov.b64 %0, {%1, %1};" : "=l"(r) : "f"(v));
    return r;
}
__device__ __forceinline__ void fma2(unsigned long long& d,
                                     unsigned long long a, unsigned long long b) {
    asm("fma.rn.f32x2 %0, %1, %2, %0;" : "+l"(d) : "l"(a), "l"(b));
}
__device__ __forceinline__ void unpk2(unsigned long long v, float& lo, float& hi) {
    asm("mov.b64 {%0, %1}, %2;" : "=f"(lo), "=f"(hi) : "l"(v));
}

// ---------------- scratch (static device globals; no runtime allocation) ----
__device__ float g_xq[NPOINTS_TOTAL * DIM];
__device__ float g_xk[NPOINTS_TOTAL * DIM];
__device__ float g_xv[NPOINTS_TOTAL * DIM];
__device__ int   g_idx[NPOINTS_TOTAL * KNN];

// ============================================================================
// KNN kernel: REVERTED verbatim to the R9 passing version (172 us).
// ============================================================================
__global__ void __launch_bounds__(256) knn_kernel(const float* __restrict__ pos) {
    const int b    = blockIdx.x >> 10;
    const int blk  = blockIdx.x & 1023;
    const int wid  = threadIdx.x >> 5;
    const int lane = threadIdx.x & 31;
    const int n    = blk * 8 + wid;
    const unsigned FULL = 0xffffffffu;

    const float* posb = pos + (size_t)b * NPTS * 3;
    __shared__ float4 tile[1024];

    const float qx = posb[n * 3 + 0];
    const float qy = posb[n * 3 + 1];
    const float qz = posb[n * 3 + 2];
    const float sqq = __fadd_rn(__fadd_rn(__fmul_rn(qx, qx), __fmul_rn(qy, qy)),
                                __fmul_rn(qz, qz));

    float kd = 1e30f;
    int   ki = 0x7fffffff;
    float thr   = 1e30f;
    int   thrid = 0x7fffffff;

    for (int base = 0; base < NPTS; base += 1024) {
        __syncthreads();
        for (int t = threadIdx.x; t < 1024; t += 256) {
            const int j = base + t;
            const float px = posb[j * 3 + 0];
            const float py = posb[j * 3 + 1];
            const float pz = posb[j * 3 + 2];
            const float sq = __fadd_rn(__fadd_rn(__fmul_rn(px, px), __fmul_rn(py, py)),
                                       __fmul_rn(pz, pz));
            tile[t] = make_float4(px, py, pz, sq);
        }
        __syncthreads();

#pragma unroll 2
        for (int it = 0; it < 8; it++) {
            const int t = it * 128 + lane;
            const float4 p0 = tile[t];
            const float4 p1 = tile[t + 32];
            const float4 p2 = tile[t + 64];
            const float4 p3 = tile[t + 96];
            const float dot0 = __fadd_rn(__fadd_rn(__fmul_rn(qx, p0.x), __fmul_rn(qy, p0.y)), __fmul_rn(qz, p0.z));
            const float dot1 = __fadd_rn(__fadd_rn(__fmul_rn(qx, p1.x), __fmul_rn(qy, p1.y)), __fmul_rn(qz, p1.z));
            const float dot2 = __fadd_rn(__fadd_rn(__fmul_rn(qx, p2.x), __fmul_rn(qy, p2.y)), __fmul_rn(qz, p2.z));
            const float dot3 = __fadd_rn(__fadd_rn(__fmul_rn(qx, p3.x), __fmul_rn(qy, p3.y)), __fmul_rn(qz, p3.z));
            const float d2_0 = __fsub_rn(__fadd_rn(sqq, p0.w), __fmul_rn(2.0f, dot0));
            const float d2_1 = __fsub_rn(__fadd_rn(sqq, p1.w), __fmul_rn(2.0f, dot1));
            const float d2_2 = __fsub_rn(__fadd_rn(sqq, p2.w), __fmul_rn(2.0f, dot2));
            const float d2_3 = __fsub_rn(__fadd_rn(sqq, p3.w), __fmul_rn(2.0f, dot3));

            const float dmin = fminf(fminf(d2_0, d2_1), fminf(d2_2, d2_3));
            if (__ballot_sync(FULL, dmin <= thr)) {
#pragma unroll
                for (int c = 0; c < 4; c++) {
                    const float d2 = (c == 0) ? d2_0 : (c == 1) ? d2_1 : (c == 2) ? d2_2 : d2_3;
                    const int   j  = base + t + 32 * c;
                    const bool qual = (d2 < thr) || (d2 == thr && j < thrid);
                    unsigned mask = __ballot_sync(FULL, qual);
                    while (mask) {
                        const int src = __ffs(mask) - 1;
                        mask &= mask - 1;
                        const float nd = __shfl_sync(FULL, d2, src);
                        const int   nj = __shfl_sync(FULL, j, src);
                        if (nd < thr || (nd == thr && nj < thrid)) {
                            const bool less = (kd < nd) || (kd == nd && ki < nj);
                            const unsigned lm = __ballot_sync(FULL, less && (lane < 16));
                            const int pos = __popc(lm);
                            const float upkd = __shfl_up_sync(FULL, kd, 1);
                            const int   upki = __shfl_up_sync(FULL, ki, 1);
                            if (lane >= pos) {
                                if (lane == pos) { kd = nd; ki = nj; }
                                else             { kd = upkd; ki = upki; }
                            }
                            thr   = __shfl_sync(FULL, kd, 15);
                            thrid = __shfl_sync(FULL, ki, 15);
                        }
                    }
                }
            }
        }
    }

    if (lane < 16) g_idx[((b << 13) + n) * KNN + lane] = ki;
}

// ============================================================================
// Projection kernel (unchanged).
// ============================================================================
struct ProjSmem {
    float WqT[64 * 68];
    float WkT[64 * 68];
    float WvT[64 * 68];
    float xs[16 * 68];
};

__global__ void __launch_bounds__(1024) proj_kernel(const float* __restrict__ x,
                                                    const float* __restrict__ Wq,
                                                    const float* __restrict__ Wk,
                                                    const float* __restrict__ Wv) {
    extern __shared__ __align__(16) unsigned char proj_raw[];
    ProjSmem* S = reinterpret_cast<ProjSmem*>(proj_raw);

    const int tid = threadIdx.x;
    const int r = tid >> 6;
    const int d = tid & 63;

    for (int e = tid; e < 4096; e += 1024) {
        const int i = e >> 6, c = e & 63;
        S->WqT[c * 68 + i] = tf32r(Wq[e]);
        S->WkT[c * 68 + i] = tf32r(Wk[e]);
        S->WvT[c * 68 + i] = tf32r(Wv[e]);
    }
    const size_t rowbase = (size_t)blockIdx.x * 16;
    for (int e = tid; e < 16 * 64; e += 1024) {
        const int rr = e >> 6, c = e & 63;
        S->xs[rr * 68 + c] = tf32r(x[(rowbase + rr) * 64 + c]);
    }
    __syncthreads();

    const float4* xv4 = (const float4*)(S->xs + r * 68);
    const float4* wq4 = (const float4*)(S->WqT + d * 68);
    const float4* wk4 = (const float4*)(S->WkT + d * 68);
    const float4* wv4 = (const float4*)(S->WvT + d * 68);
    float aq = 0.f, ak = 0.f, av = 0.f;
#pragma unroll
    for (int i = 0; i < 16; i++) {
        const float4 xv = xv4[i];
        const float4 wq = wq4[i];
        const float4 wk = wk4[i];
        const float4 wv = wv4[i];
        aq = fmaf(wq.x, xv.x, aq); aq = fmaf(wq.y, xv.y, aq);
        aq = fmaf(wq.z, xv.z, aq); aq = fmaf(wq.w, xv.w, aq);
        ak = fmaf(wk.x, xv.x, ak); ak = fmaf(wk.y, xv.y, ak);
        ak = fmaf(wk.z, xv.z, ak); ak = fmaf(wk.w, xv.w, ak);
        av = fmaf(wv.x, xv.x, av); av = fmaf(wv.y, xv.y, av);
        av = fmaf(wv.z, xv.z, av); av = fmaf(wv.w, xv.w, av);
    }
    const size_t o = (rowbase + r) * 64 + d;
    g_xq[o] = aq; g_xk[o] = ak; g_xv[o] = av;
}

// ============================================================================
// Attention kernel v6: fp32x2 GEMM, ALL weights staged upfront, single act
// buffer (extra post-read syncs replace mid-kernel staging). Tiling, rounding
// points and accumulation orders identical to the passing R9 attn.
// ============================================================================
struct AttnSmem {
    float act[128 * 68];       // 34816 B
    float w[4][64 * 68];       // P2, A1, A2, Wf  (69632 B)
    float qs[PPB * 68];
    float agg[PPB * 68];
    float rel[128 * 4];
    float P1s[3 * 64];
    float pb1s[64], pb2s[64], ab1s[64], ab2s[64], bfs[64];
};

__global__ void __launch_bounds__(256, 2) attn_kernel(
    const float* __restrict__ x,
    const float* __restrict__ pos,
    const float* __restrict__ P1,
    const float* __restrict__ pb1,
    const float* __restrict__ P2,
    const float* __restrict__ pb2,
    const float* __restrict__ A1,
    const float* __restrict__ ab1,
    const float* __restrict__ A2,
    const float* __restrict__ ab2,
    const float* __restrict__ Wf,
    const float* __restrict__ bf,
    float* __restrict__ out) {
    extern __shared__ __align__(16) unsigned char attn_raw[];
    AttnSmem* S = reinterpret_cast<AttnSmem*>(attn_raw);

    const int tid = threadIdx.x;
    const int tx  = tid & 15;
    const int ty  = tid >> 4;
    const int n0  = tx * 4;
    const int m0  = ty * 8;
    const int p   = ty >> 1;
    const int pbase = blockIdx.x * PPB;
    const int b   = pbase >> 13;

    // ---- stage EVERYTHING upfront (LDG latency overlaps across streams) ----
    for (int e = tid; e < 4096; e += 256) {
        const int k = e >> 6, c = e & 63;
        S->w[0][k * 68 + c] = tf32r(P2[e]);
        S->w[1][k * 68 + c] = tf32r(A1[e]);
        S->w[2][k * 68 + c] = tf32r(A2[e]);
        S->w[3][k * 68 + c] = tf32r(Wf[e]);
    }
    if (tid < 192) S->P1s[tid] = P1[tid];
    if (tid < 64) {
        S->pb1s[tid] = pb1[tid];
        S->pb2s[tid] = pb2[tid];
        S->ab1s[tid] = ab1[tid];
        S->ab2s[tid] = ab2[tid];
        S->bfs[tid]  = bf[tid];
    }
    for (int e = tid; e < PPB * 64; e += 256)
        S->qs[(e >> 6) * 68 + (e & 63)] = g_xq[(size_t)pbase * 64 + e];

    int grow[8];
#pragma unroll
    for (int r = 0; r < 8; r++)
        grow[r] = (b << 13) + g_idx[pbase * KNN + m0 + r];

    for (int e = tid; e < 128 * 3; e += 256) {
        const int m = e / 3, c = e % 3;
        const int pp = m >> 4;
        const int nb = g_idx[pbase * KNN + m];
        S->rel[m * 4 + c] = pos[(size_t)(pbase + pp) * 3 + c]
                          - pos[((size_t)(b << 13) + nb) * 3 + c];
    }
    __syncthreads();

    // ---- hidden = relu(rel @ P1 + pb1) -> act ----
    {
        float4* a4 = (float4*)(S->act);
#pragma unroll
        for (int r = 0; r < 8; r++) {
            const int m = m0 + r;
            const float r0 = S->rel[m * 4 + 0];
            const float r1 = S->rel[m * 4 + 1];
            const float r2 = S->rel[m * 4 + 2];
            float4 hv;
#pragma unroll
            for (int c = 0; c < 4; c++) {
                const int n = n0 + c;
                const float dotp = __fadd_rn(__fadd_rn(__fmul_rn(r0, S->P1s[n]),
                                                       __fmul_rn(r1, S->P1s[64 + n])),
                                             __fmul_rn(r2, S->P1s[128 + n]));
                const float hd = __fadd_rn(dotp, S->pb1s[n]);
                ((float*)&hv)[c] = tf32r(fmaxf(hd, 0.f));
            }
            a4[m * 17 + tx] = hv;
        }
    }
    __syncthreads();

    unsigned long long acc2[8][2];
    float pe[8][4];

#define ACC_INIT(BIAS)                                                        \
    {                                                                         \
        const unsigned long long b01 = pk2((BIAS)[n0 + 0], (BIAS)[n0 + 1]);   \
        const unsigned long long b23 = pk2((BIAS)[n0 + 2], (BIAS)[n0 + 3]);   \
        _Pragma("unroll")                                                     \
        for (int r = 0; r < 8; r++) { acc2[r][0] = b01; acc2[r][1] = b23; }   \
    }

#define GEMM_PHASE(WIDX)                                                      \
    {                                                                         \
        const ulonglong2* wb2 = (const ulonglong2*)(S->w[WIDX]);              \
        const float4* in4 = (const float4*)(S->act);                          \
        _Pragma("unroll 2")                                                   \
        for (int kq = 0; kq < 16; kq++) {                                     \
            const ulonglong2 W0 = wb2[(4 * kq + 0) * 17 + tx];                \
            const ulonglong2 W1 = wb2[(4 * kq + 1) * 17 + tx];                \
            const ulonglong2 W2 = wb2[(4 * kq + 2) * 17 + tx];                \
            const ulonglong2 W3 = wb2[(4 * kq + 3) * 17 + tx];                \
            _Pragma("unroll")                                                 \
            for (int r = 0; r < 8; r++) {                                     \
                const float4 a = in4[(m0 + r) * 17 + kq];                     \
                const unsigned long long ax = splat2(a.x);                    \
                const unsigned long long ay = splat2(a.y);                    \
                const unsigned long long az = splat2(a.z);                    \
                const unsigned long long aw = splat2(a.w);                    \
                fma2(acc2[r][0], ax, W0.x); fma2(acc2[r][1], ax, W0.y);       \
                fma2(acc2[r][0], ay, W1.x); fma2(acc2[r][1], ay, W1.y);       \
                fma2(acc2[r][0], az, W2.x); fma2(acc2[r][1], az, W2.y);       \
                fma2(acc2[r][0], aw, W3.x); fma2(acc2[r][1], aw, W3.y);       \
            }                                                                 \
        }                                                                     \
    }

    // ---- GEMM1: pe = hidden @ P2 + pb2 ; h = q - k + pe -> act ----
    ACC_INIT(S->pb2s);
    GEMM_PHASE(0);
    __syncthreads();   // all reads of act (hidden) complete before overwrite
    {
        const float4 qv = ((const float4*)(S->qs))[p * 17 + tx];
        float4* a4 = (float4*)(S->act);
#pragma unroll
        for (int r = 0; r < 8; r++) {
            unpk2(acc2[r][0], pe[r][0], pe[r][1]);
            unpk2(acc2[r][1], pe[r][2], pe[r][3]);
            const float4 kv = *(const float4*)(g_xk + (size_t)grow[r] * 64 + n0);
            float4 hv;
            hv.x = tf32r(qv.x - kv.x + pe[r][0]);
            hv.y = tf32r(qv.y - kv.y + pe[r][1]);
            hv.z = tf32r(qv.z - kv.z + pe[r][2]);
            hv.w = tf32r(qv.w - kv.w + pe[r][3]);
            a4[(m0 + r) * 17 + tx] = hv;
        }
    }
    __syncthreads();

    // ---- GEMM2: t = relu(h @ A1 + ab1) -> act ----
    ACC_INIT(S->ab1s);
    GEMM_PHASE(1);
    __syncthreads();
    {
        float4* a4 = (float4*)(S->act);
#pragma unroll
        for (int r = 0; r < 8; r++) {
            float t0, t1, t2, t3;
            unpk2(acc2[r][0], t0, t1);
            unpk2(acc2[r][1], t2, t3);
            float4 tv;
            tv.x = tf32r(fmaxf(t0, 0.f));
            tv.y = tf32r(fmaxf(t1, 0.f));
            tv.z = tf32r(fmaxf(t2, 0.f));
            tv.w = tf32r(fmaxf(t3, 0.f));
            a4[(m0 + r) * 17 + tx] = tv;
        }
    }
    __syncthreads();

    // ---- GEMM3: a = t @ A2 + ab2 ; softmax ; agg ----
    ACC_INIT(S->ab2s);
    GEMM_PHASE(2);
    {
        float acc[8][4];
#pragma unroll
        for (int r = 0; r < 8; r++) {
            unpk2(acc2[r][0], acc[r][0], acc[r][1]);
            unpk2(acc2[r][1], acc[r][2], acc[r][3]);
        }
        float ev[8][4];
#pragma unroll
        for (int c = 0; c < 4; c++) {
            float m = acc[0][c];
#pragma unroll
            for (int r = 1; r < 8; r++) m = fmaxf(m, acc[r][c]);
            const float om = __shfl_xor_sync(0xffffffffu, m, 16);
            m = fmaxf(m, om);
            float s = 0.f;
#pragma unroll
            for (int r = 0; r < 8; r++) {
                ev[r][c] = __expf((acc[r][c] - m) * 0.125f);
                s += ev[r][c];
            }
            s += __shfl_xor_sync(0xffffffffu, s, 16);
#pragma unroll
            for (int r = 0; r < 8; r++) ev[r][c] /= s;
        }
        float ag[4] = {0.f, 0.f, 0.f, 0.f};
#pragma unroll
        for (int r = 0; r < 8; r++) {
            const float4 vv = *(const float4*)(g_xv + (size_t)grow[r] * 64 + n0);
            ag[0] += ev[r][0] * (vv.x + pe[r][0]);
            ag[1] += ev[r][1] * (vv.y + pe[r][1]);
            ag[2] += ev[r][2] * (vv.z + pe[r][2]);
            ag[3] += ev[r][3] * (vv.w + pe[r][3]);
        }
#pragma unroll
        for (int c = 0; c < 4; c++)
            ag[c] += __shfl_xor_sync(0xffffffffu, ag[c], 16);
        if ((ty & 1) == 0) {
            float4 av;
            av.x = tf32r(ag[0]); av.y = tf32r(ag[1]);
            av.z = tf32r(ag[2]); av.w = tf32r(ag[3]);
            ((float4*)(S->agg))[p * 17 + tx] = av;
        }
    }
    __syncthreads();

    // ---- out = agg @ Wf + bf + x ----
#pragma unroll
    for (int t2 = 0; t2 < 2; t2++) {
        const int oi = tid + 256 * t2;
        const int pp = oi >> 6;
        const int n  = oi & 63;
        float o = S->bfs[n] + x[(size_t)(pbase + pp) * 64 + n];
        const float* ar = S->agg + pp * 68;
        const float* wf = S->w[3];
#pragma unroll
        for (int k = 0; k < 64; k++)
            o = fmaf(ar[k], wf[k * 68 + n], o);
        out[(size_t)(pbase + pp) * 64 + n] = o;
    }
#undef GEMM_PHASE
#undef ACC_INIT
}

// ============================================================================
// launch
// ============================================================================
extern "C" void kernel_launch(void* const* d_in, const int* in_sizes, int n_in,
                              void* d_out, int out_size) {
    const float* x   = (const float*)d_in[0];
    const float* pos = (const float*)d_in[1];
    const float* Wq  = (const float*)d_in[2];
    const float* Wk  = (const float*)d_in[3];
    const float* Wv  = (const float*)d_in[4];
    const float* P1  = (const float*)d_in[5];
    const float* pb1 = (const float*)d_in[6];
    const float* P2  = (const float*)d_in[7];
    const float* pb2 = (const float*)d_in[8];
    const float* A1  = (const float*)d_in[9];
    const float* ab1 = (const float*)d_in[10];
    const float* A2  = (const float*)d_in[11];
    const float* ab2 = (const float*)d_in[12];
    const float* Wf  = (const float*)d_in[13];
    const float* bf  = (const float*)d_in[14];
    float* out = (float*)d_out;

    cudaFuncSetAttribute(proj_kernel, cudaFuncAttributeMaxDynamicSharedMemorySize,
                         (int)sizeof(ProjSmem));
    cudaFuncSetAttribute(attn_kernel, cudaFuncAttributeMaxDynamicSharedMemorySize,
                         (int)sizeof(AttnSmem));

    knn_kernel<<<2048, 256>>>(pos);
    proj_kernel<<<1024, 1024, sizeof(ProjSmem)>>>(x, Wq, Wk, Wv);
    attn_kernel<<<NPOINTS_TOTAL / PPB, 256, sizeof(AttnSmem)>>>(
        x, pos, P1, pb1, P2, pb2, A1, ab1, A2, ab2, Wf, bf, out);
}

// round 14
// speedup vs baseline: 1.5711x; 1.2640x over previous
#include <cuda_runtime.h>
#include <cuda_bf16.h>
#include <cstddef>
#include <cstdint>

#define BATCH 2
#define NPTS  8192
#define DIM   64
#define KNN   16
#define NPOINTS_TOTAL (BATCH * NPTS)
#define PPB   8    // points per attn block (128 rows)

#define GRID_RES 16
#define NCELLS   (GRID_RES * GRID_RES * GRID_RES)   // 4096
#define CELL_H   (1.0f / GRID_RES)
#define CAP      640   // per-warp candidate buffer (ints)

// tf32 operand rounding for the K=64 GEMMs (cublas tf32 path emulation).
__device__ __forceinline__ float tf32r(float x) {
    uint32_t y;
    asm("cvt.rna.tf32.f32 %0, %1;" : "=r"(y) : "f"(x));
    return __uint_as_float(y);
}

// ---- packed fp32x2 helpers (Blackwell dual-fp32 pipe) ----
__device__ __forceinline__ unsigned long long pk2(float lo, float hi) {
    unsigned long long r;
    asm("mov.b64 %0, {%1, %2};" : "=l"(r) : "f"(lo), "f"(hi));
    return r;
}
__device__ __forceinline__ unsigned long long splat2(float v) {
    unsigned long long r;
    asm("mov.b64 %0, {%1, %1};" : "=l"(r) : "f"(v));
    return r;
}
__device__ __forceinline__ void fma2(unsigned long long& d,
                                     unsigned long long a, unsigned long long b) {
    asm("fma.rn.f32x2 %0, %1, %2, %0;" : "+l"(d) : "l"(a), "l"(b));
}
__device__ __forceinline__ void unpk2(unsigned long long v, float& lo, float& hi) {
    asm("mov.b64 {%0, %1}, %2;" : "=f"(lo), "=f"(hi) : "l"(v));
}

// ---------------- scratch (static device globals; no runtime allocation) ----
__device__ float g_xq[NPOINTS_TOTAL * DIM];
__device__ float g_xk[NPOINTS_TOTAL * DIM];
__device__ float g_xv[NPOINTS_TOTAL * DIM];
__device__ int   g_idx[NPOINTS_TOTAL * KNN];

__device__ int    g_cellcnt[BATCH * NCELLS];
__device__ int    g_cellstart[BATCH * NCELLS];
__device__ int    g_cursor[BATCH * NCELLS];
__device__ float4 g_bpos[BATCH * NPTS];
__device__ int    g_bidx[BATCH * NPTS];

__device__ __forceinline__ int cell_of(float x, float y, float z) {
    int cx = (int)(x * GRID_RES); cx = cx < 0 ? 0 : (cx > GRID_RES - 1 ? GRID_RES - 1 : cx);
    int cy = (int)(y * GRID_RES); cy = cy < 0 ? 0 : (cy > GRID_RES - 1 ? GRID_RES - 1 : cy);
    int cz = (int)(z * GRID_RES); cz = cz < 0 ? 0 : (cz > GRID_RES - 1 ? GRID_RES - 1 : cz);
    return (cz * GRID_RES + cy) * GRID_RES + cx;
}

// ---- binning kernels ----
__global__ void bin_zero() {
    const int i = blockIdx.x * 256 + threadIdx.x;
    if (i < BATCH * NCELLS) g_cellcnt[i] = 0;
}

__global__ void bin_count(const float* __restrict__ pos) {
    const int i = blockIdx.x * 256 + threadIdx.x;   // 0..16383
    const float x = pos[i * 3 + 0];
    const float y = pos[i * 3 + 1];
    const float z = pos[i * 3 + 2];
    const int b = i >> 13;
    atomicAdd(&g_cellcnt[b * NCELLS + cell_of(x, y, z)], 1);
}

__global__ void bin_scan() {   // one block per batch, 1024 threads, 4 cells each
    __shared__ int sc[1024];
    const int b = blockIdx.x;
    const int t = threadIdx.x;
    const int base = b * NCELLS + t * 4;
    const int c0 = g_cellcnt[base + 0];
    const int c1 = g_cellcnt[base + 1];
    const int c2 = g_cellcnt[base + 2];
    const int c3 = g_cellcnt[base + 3];
    const int own = c0 + c1 + c2 + c3;
    sc[t] = own;
    __syncthreads();
    int incl = own;
    for (int off = 1; off < 1024; off <<= 1) {
        const int u = (t >= off) ? sc[t - off] : 0;
        __syncthreads();
        incl += u;
        sc[t] = incl;
        __syncthreads();
    }
    const int excl = incl - own;
    const int gb = b * NPTS;
    g_cellstart[base + 0] = gb + excl;
    g_cellstart[base + 1] = gb + excl + c0;
    g_cellstart[base + 2] = gb + excl + c0 + c1;
    g_cellstart[base + 3] = gb + excl + c0 + c1 + c2;
    g_cursor[base + 0] = gb + excl;
    g_cursor[base + 1] = gb + excl + c0;
    g_cursor[base + 2] = gb + excl + c0 + c1;
    g_cursor[base + 3] = gb + excl + c0 + c1 + c2;
}

__global__ void bin_scatter(const float* __restrict__ pos) {
    const int i = blockIdx.x * 256 + threadIdx.x;   // 0..16383
    const float x = pos[i * 3 + 0];
    const float y = pos[i * 3 + 1];
    const float z = pos[i * 3 + 2];
    const float sq = __fadd_rn(__fadd_rn(__fmul_rn(x, x), __fmul_rn(y, y)),
                               __fmul_rn(z, z));
    const int b = i >> 13;
    const int slot = atomicAdd(&g_cursor[b * NCELLS + cell_of(x, y, z)], 1);
    g_bpos[slot] = make_float4(x, y, z, sq);
    g_bidx[slot] = i & (NPTS - 1);
}

// ============================================================================
// KNN search: grid cells, one warp per query. Exact: same d2 formula and
// (d2, idx) lexicographic insert as the passing brute-force kernels; the
// ring bound guarantees the candidate set contains the true top-16.
// ============================================================================
__global__ void __launch_bounds__(256) knn_kernel(const float* __restrict__ pos) {
    const int b    = blockIdx.x >> 10;
    const int blk  = blockIdx.x & 1023;
    const int w    = threadIdx.x >> 5;
    const int lane = threadIdx.x & 31;
    const int n    = blk * 8 + w;
    const unsigned FULL = 0xffffffffu;

    const float qx = pos[((size_t)b * NPTS + n) * 3 + 0];
    const float qy = pos[((size_t)b * NPTS + n) * 3 + 1];
    const float qz = pos[((size_t)b * NPTS + n) * 3 + 2];
    const float sqq = __fadd_rn(__fadd_rn(__fmul_rn(qx, qx), __fmul_rn(qy, qy)),
                                __fmul_rn(qz, qz));

    int cqx = (int)(qx * GRID_RES); cqx = cqx < 0 ? 0 : (cqx > 15 ? 15 : cqx);
    int cqy = (int)(qy * GRID_RES); cqy = cqy < 0 ? 0 : (cqy > 15 ? 15 : cqy);
    int cqz = (int)(qz * GRID_RES); cqz = cqz < 0 ? 0 : (cqz > 15 ? 15 : cqz);

    __shared__ int buf[8][CAP];

    float kd = 1e30f;
    int   ki = 0x7fffffff;
    float thr   = 1e30f;
    int   thrid = 0x7fffffff;

    const int cbase = b * NCELLS;

    for (int R = 2; ; R++) {
        const int side = 2 * R + 1;
        const int ncc  = side * side * side;
        for (int cb = 0; cb < ncc; cb += 32) {
            const int ci = cb + lane;
            int cnt = 0, start = 0;
            if (ci < ncc) {
                const int dz0 = ci / (side * side);
                const int rem = ci - dz0 * side * side;
                const int dy0 = rem / side;
                const int dx0 = rem - dy0 * side;
                const int dx = dx0 - R, dy = dy0 - R, dz = dz0 - R;
                const int adx = dx < 0 ? -dx : dx;
                const int ady = dy < 0 ? -dy : dy;
                const int adz = dz < 0 ? -dz : dz;
                const int cheb = adx > ady ? (adx > adz ? adx : adz) : (ady > adz ? ady : adz);
                if (R == 2 || cheb == R) {   // ring-only for R>2 (inner done)
                    const int cx = cqx + dx, cy = cqy + dy, cz = cqz + dz;
                    if (cx >= 0 && cx < GRID_RES && cy >= 0 && cy < GRID_RES &&
                        cz >= 0 && cz < GRID_RES) {
                        const int cell = cbase + (cz * GRID_RES + cy) * GRID_RES + cx;
                        cnt   = g_cellcnt[cell];
                        start = g_cellstart[cell];
                    }
                }
            }
            // warp exclusive scan of cnt
            int incl = cnt;
#pragma unroll
            for (int off = 1; off < 32; off <<= 1) {
                const int u = __shfl_up_sync(FULL, incl, off);
                if (lane >= off) incl += u;
            }
            int total = __shfl_sync(FULL, incl, 31);
            const int excl = incl - cnt;
            for (int t2 = 0; t2 < cnt; t2++) {
                const int o = excl + t2;
                if (o < CAP) buf[w][o] = start + t2;
            }
            __syncwarp();
            if (total > CAP) total = CAP;

            for (int bb = 0; bb < total; bb += 32) {
                const int o = bb + lane;
                float d2 = 1e30f;
                int   j  = 0x7fffffff;
                bool qual = false;
                if (o < total) {
                    const int slot = buf[w][o];
                    const float4 p = g_bpos[slot];
                    j = g_bidx[slot];
                    const float dot = __fadd_rn(__fadd_rn(__fmul_rn(qx, p.x),
                                                          __fmul_rn(qy, p.y)),
                                                __fmul_rn(qz, p.z));
                    d2 = __fsub_rn(__fadd_rn(sqq, p.w), __fmul_rn(2.0f, dot));
                    qual = (d2 < thr) || (d2 == thr && j < thrid);
                }
                unsigned mask = __ballot_sync(FULL, qual);
                while (mask) {
                    const int src = __ffs(mask) - 1;
                    mask &= mask - 1;
                    const float nd = __shfl_sync(FULL, d2, src);
                    const int   nj = __shfl_sync(FULL, j, src);
                    if (nd < thr || (nd == thr && nj < thrid)) {
                        const bool less = (kd < nd) || (kd == nd && ki < nj);
                        const unsigned lm = __ballot_sync(FULL, less && (lane < 16));
                        const int pos2 = __popc(lm);
                        const float upkd = __shfl_up_sync(FULL, kd, 1);
                        const int   upki = __shfl_up_sync(FULL, ki, 1);
                        if (lane >= pos2) {
                            if (lane == pos2) { kd = nd; ki = nj; }
                            else              { kd = upkd; ki = upki; }
                        }
                        thr   = __shfl_sync(FULL, kd, 15);
                        thrid = __shfl_sync(FULL, ki, 15);
                    }
                }
            }
            __syncwarp();   // buf reads done before next stage overwrites
        }
        // ring R complete: unexamined points have true dist > R*h
        const float bound = (float)R * CELL_H;
        if (thr < bound * bound - 1e-5f) break;   // 16 found & provably complete
        if (R >= GRID_RES) break;                 // whole grid covered
    }

    if (lane < 16) g_idx[((b << 13) + n) * KNN + lane] = ki;
}

// ============================================================================
// Projection kernel (unchanged).
// ============================================================================
struct ProjSmem {
    float WqT[64 * 68];
    float WkT[64 * 68];
    float WvT[64 * 68];
    float xs[16 * 68];
};

__global__ void __launch_bounds__(1024) proj_kernel(const float* __restrict__ x,
                                                    const float* __restrict__ Wq,
                                                    const float* __restrict__ Wk,
                                                    const float* __restrict__ Wv) {
    extern __shared__ __align__(16) unsigned char proj_raw[];
    ProjSmem* S = reinterpret_cast<ProjSmem*>(proj_raw);

    const int tid = threadIdx.x;
    const int r = tid >> 6;
    const int d = tid & 63;

    for (int e = tid; e < 4096; e += 1024) {
        const int i = e >> 6, c = e & 63;
        S->WqT[c * 68 + i] = tf32r(Wq[e]);
        S->WkT[c * 68 + i] = tf32r(Wk[e]);
        S->WvT[c * 68 + i] = tf32r(Wv[e]);
    }
    const size_t rowbase = (size_t)blockIdx.x * 16;
    for (int e = tid; e < 16 * 64; e += 1024) {
        const int rr = e >> 6, c = e & 63;
        S->xs[rr * 68 + c] = tf32r(x[(rowbase + rr) * 64 + c]);
    }
    __syncthreads();

    const float4* xv4 = (const float4*)(S->xs + r * 68);
    const float4* wq4 = (const float4*)(S->WqT + d * 68);
    const float4* wk4 = (const float4*)(S->WkT + d * 68);
    const float4* wv4 = (const float4*)(S->WvT + d * 68);
    float aq = 0.f, ak = 0.f, av = 0.f;
#pragma unroll
    for (int i = 0; i < 16; i++) {
        const float4 xv = xv4[i];
        const float4 wq = wq4[i];
        const float4 wk = wk4[i];
        const float4 wv = wv4[i];
        aq = fmaf(wq.x, xv.x, aq); aq = fmaf(wq.y, xv.y, aq);
        aq = fmaf(wq.z, xv.z, aq); aq = fmaf(wq.w, xv.w, aq);
        ak = fmaf(wk.x, xv.x, ak); ak = fmaf(wk.y, xv.y, ak);
        ak = fmaf(wk.z, xv.z, ak); ak = fmaf(wk.w, xv.w, ak);
        av = fmaf(wv.x, xv.x, av); av = fmaf(wv.y, xv.y, av);
        av = fmaf(wv.z, xv.z, av); av = fmaf(wv.w, xv.w, av);
    }
    const size_t o = (rowbase + r) * 64 + d;
    g_xq[o] = aq; g_xk[o] = ak; g_xv[o] = av;
}

// ============================================================================
// Attention kernel v6 (unchanged from passing R13).
// ============================================================================
struct AttnSmem {
    float act[128 * 68];
    float w[4][64 * 68];
    float qs[PPB * 68];
    float agg[PPB * 68];
    float rel[128 * 4];
    float P1s[3 * 64];
    float pb1s[64], pb2s[64], ab1s[64], ab2s[64], bfs[64];
};

__global__ void __launch_bounds__(256, 2) attn_kernel(
    const float* __restrict__ x,
    const float* __restrict__ pos,
    const float* __restrict__ P1,
    const float* __restrict__ pb1,
    const float* __restrict__ P2,
    const float* __restrict__ pb2,
    const float* __restrict__ A1,
    const float* __restrict__ ab1,
    const float* __restrict__ A2,
    const float* __restrict__ ab2,
    const float* __restrict__ Wf,
    const float* __restrict__ bf,
    float* __restrict__ out) {
    extern __shared__ __align__(16) unsigned char attn_raw[];
    AttnSmem* S = reinterpret_cast<AttnSmem*>(attn_raw);

    const int tid = threadIdx.x;
    const int tx  = tid & 15;
    const int ty  = tid >> 4;
    const int n0  = tx * 4;
    const int m0  = ty * 8;
    const int p   = ty >> 1;
    const int pbase = blockIdx.x * PPB;
    const int b   = pbase >> 13;

    for (int e = tid; e < 4096; e += 256) {
        const int k = e >> 6, c = e & 63;
        S->w[0][k * 68 + c] = tf32r(P2[e]);
        S->w[1][k * 68 + c] = tf32r(A1[e]);
        S->w[2][k * 68 + c] = tf32r(A2[e]);
        S->w[3][k * 68 + c] = tf32r(Wf[e]);
    }
    if (tid < 192) S->P1s[tid] = P1[tid];
    if (tid < 64) {
        S->pb1s[tid] = pb1[tid];
        S->pb2s[tid] = pb2[tid];
        S->ab1s[tid] = ab1[tid];
        S->ab2s[tid] = ab2[tid];
        S->bfs[tid]  = bf[tid];
    }
    for (int e = tid; e < PPB * 64; e += 256)
        S->qs[(e >> 6) * 68 + (e & 63)] = g_xq[(size_t)pbase * 64 + e];

    int grow[8];
#pragma unroll
    for (int r = 0; r < 8; r++)
        grow[r] = (b << 13) + g_idx[pbase * KNN + m0 + r];

    for (int e = tid; e < 128 * 3; e += 256) {
        const int m = e / 3, c = e % 3;
        const int pp = m >> 4;
        const int nb = g_idx[pbase * KNN + m];
        S->rel[m * 4 + c] = pos[(size_t)(pbase + pp) * 3 + c]
                          - pos[((size_t)(b << 13) + nb) * 3 + c];
    }
    __syncthreads();

    {
        float4* a4 = (float4*)(S->act);
#pragma unroll
        for (int r = 0; r < 8; r++) {
            const int m = m0 + r;
            const float r0 = S->rel[m * 4 + 0];
            const float r1 = S->rel[m * 4 + 1];
            const float r2 = S->rel[m * 4 + 2];
            float4 hv;
#pragma unroll
            for (int c = 0; c < 4; c++) {
                const int n = n0 + c;
                const float dotp = __fadd_rn(__fadd_rn(__fmul_rn(r0, S->P1s[n]),
                                                       __fmul_rn(r1, S->P1s[64 + n])),
                                             __fmul_rn(r2, S->P1s[128 + n]));
                const float hd = __fadd_rn(dotp, S->pb1s[n]);
                ((float*)&hv)[c] = tf32r(fmaxf(hd, 0.f));
            }
            a4[m * 17 + tx] = hv;
        }
    }
    __syncthreads();

    unsigned long long acc2[8][2];
    float pe[8][4];

#define ACC_INIT(BIAS)                                                        \
    {                                                                         \
        const unsigned long long b01 = pk2((BIAS)[n0 + 0], (BIAS)[n0 + 1]);   \
        const unsigned long long b23 = pk2((BIAS)[n0 + 2], (BIAS)[n0 + 3]);   \
        _Pragma("unroll")                                                     \
        for (int r = 0; r < 8; r++) { acc2[r][0] = b01; acc2[r][1] = b23; }   \
    }

#define GEMM_PHASE(WIDX)                                                      \
    {                                                                         \
        const ulonglong2* wb2 = (const ulonglong2*)(S->w[WIDX]);              \
        const float4* in4 = (const float4*)(S->act);                          \
        _Pragma("unroll 2")                                                   \
        for (int kq = 0; kq < 16; kq++) {                                     \
            const ulonglong2 W0 = wb2[(4 * kq + 0) * 17 + tx];                \
            const ulonglong2 W1 = wb2[(4 * kq + 1) * 17 + tx];                \
            const ulonglong2 W2 = wb2[(4 * kq + 2) * 17 + tx];                \
            const ulonglong2 W3 = wb2[(4 * kq + 3) * 17 + tx];                \
            _Pragma("unroll")                                                 \
            for (int r = 0; r < 8; r++) {                                     \
                const float4 a = in4[(m0 + r) * 17 + kq];                     \
                const unsigned long long ax = splat2(a.x);                    \
                const unsigned long long ay = splat2(a.y);                    \
                const unsigned long long az = splat2(a.z);                    \
                const unsigned long long aw = splat2(a.w);                    \
                fma2(acc2[r][0], ax, W0.x); fma2(acc2[r][1], ax, W0.y);       \
                fma2(acc2[r][0], ay, W1.x); fma2(acc2[r][1], ay, W1.y);       \
                fma2(acc2[r][0], az, W2.x); fma2(acc2[r][1], az, W2.y);       \
                fma2(acc2[r][0], aw, W3.x); fma2(acc2[r][1], aw, W3.y);       \
            }                                                                 \
        }                                                                     \
    }

    ACC_INIT(S->pb2s);
    GEMM_PHASE(0);
    __syncthreads();
    {
        const float4 qv = ((const float4*)(S->qs))[p * 17 + tx];
        float4* a4 = (float4*)(S->act);
#pragma unroll
        for (int r = 0; r < 8; r++) {
            unpk2(acc2[r][0], pe[r][0], pe[r][1]);
            unpk2(acc2[r][1], pe[r][2], pe[r][3]);
            const float4 kv = *(const float4*)(g_xk + (size_t)grow[r] * 64 + n0);
            float4 hv;
            hv.x = tf32r(qv.x - kv.x + pe[r][0]);
            hv.y = tf32r(qv.y - kv.y + pe[r][1]);
            hv.z = tf32r(qv.z - kv.z + pe[r][2]);
            hv.w = tf32r(qv.w - kv.w + pe[r][3]);
            a4[(m0 + r) * 17 + tx] = hv;
        }
    }
    __syncthreads();

    ACC_INIT(S->ab1s);
    GEMM_PHASE(1);
    __syncthreads();
    {
        float4* a4 = (float4*)(S->act);
#pragma unroll
        for (int r = 0; r < 8; r++) {
            float t0, t1, t2, t3;
            unpk2(acc2[r][0], t0, t1);
            unpk2(acc2[r][1], t2, t3);
            float4 tv;
            tv.x = tf32r(fmaxf(t0, 0.f));
            tv.y = tf32r(fmaxf(t1, 0.f));
            tv.z = tf32r(fmaxf(t2, 0.f));
            tv.w = tf32r(fmaxf(t3, 0.f));
            a4[(m0 + r) * 17 + tx] = tv;
        }
    }
    __syncthreads();

    ACC_INIT(S->ab2s);
    GEMM_PHASE(2);
    {
        float acc[8][4];
#pragma unroll
        for (int r = 0; r < 8; r++) {
            unpk2(acc2[r][0], acc[r][0], acc[r][1]);
            unpk2(acc2[r][1], acc[r][2], acc[r][3]);
        }
        float ev[8][4];
#pragma unroll
        for (int c = 0; c < 4; c++) {
            float m = acc[0][c];
#pragma unroll
            for (int r = 1; r < 8; r++) m = fmaxf(m, acc[r][c]);
            const float om = __shfl_xor_sync(0xffffffffu, m, 16);
            m = fmaxf(m, om);
            float s = 0.f;
#pragma unroll
            for (int r = 0; r < 8; r++) {
                ev[r][c] = __expf((acc[r][c] - m) * 0.125f);
                s += ev[r][c];
            }
            s += __shfl_xor_sync(0xffffffffu, s, 16);
#pragma unroll
            for (int r = 0; r < 8; r++) ev[r][c] /= s;
        }
        float ag[4] = {0.f, 0.f, 0.f, 0.f};
#pragma unroll
        for (int r = 0; r < 8; r++) {
            const float4 vv = *(const float4*)(g_xv + (size_t)grow[r] * 64 + n0);
            ag[0] += ev[r][0] * (vv.x + pe[r][0]);
            ag[1] += ev[r][1] * (vv.y + pe[r][1]);
            ag[2] += ev[r][2] * (vv.z + pe[r][2]);
            ag[3] += ev[r][3] * (vv.w + pe[r][3]);
        }
#pragma unroll
        for (int c = 0; c < 4; c++)
            ag[c] += __shfl_xor_sync(0xffffffffu, ag[c], 16);
        if ((ty & 1) == 0) {
            float4 av;
            av.x = tf32r(ag[0]); av.y = tf32r(ag[1]);
            av.z = tf32r(ag[2]); av.w = tf32r(ag[3]);
            ((float4*)(S->agg))[p * 17 + tx] = av;
        }
    }
    __syncthreads();

#pragma unroll
    for (int t2 = 0; t2 < 2; t2++) {
        const int oi = tid + 256 * t2;
        const int pp = oi >> 6;
        const int n  = oi & 63;
        float o = S->bfs[n] + x[(size_t)(pbase + pp) * 64 + n];
        const float* ar = S->agg + pp * 68;
        const float* wf = S->w[3];
#pragma unroll
        for (int k = 0; k < 64; k++)
            o = fmaf(ar[k], wf[k * 68 + n], o);
        out[(size_t)(pbase + pp) * 64 + n] = o;
    }
#undef GEMM_PHASE
#undef ACC_INIT
}

// ============================================================================
// launch
// ============================================================================
extern "C" void kernel_launch(void* const* d_in, const int* in_sizes, int n_in,
                              void* d_out, int out_size) {
    const float* x   = (const float*)d_in[0];
    const float* pos = (const float*)d_in[1];
    const float* Wq  = (const float*)d_in[2];
    const float* Wk  = (const float*)d_in[3];
    const float* Wv  = (const float*)d_in[4];
    const float* P1  = (const float*)d_in[5];
    const float* pb1 = (const float*)d_in[6];
    const float* P2  = (const float*)d_in[7];
    const float* pb2 = (const float*)d_in[8];
    const float* A1  = (const float*)d_in[9];
    const float* ab1 = (const float*)d_in[10];
    const float* A2  = (const float*)d_in[11];
    const float* ab2 = (const float*)d_in[12];
    const float* Wf  = (const float*)d_in[13];
    const float* bf  = (const float*)d_in[14];
    float* out = (float*)d_out;

    cudaFuncSetAttribute(proj_kernel, cudaFuncAttributeMaxDynamicSharedMemorySize,
                         (int)sizeof(ProjSmem));
    cudaFuncSetAttribute(attn_kernel, cudaFuncAttributeMaxDynamicSharedMemorySize,
                         (int)sizeof(AttnSmem));

    bin_zero<<<(BATCH * NCELLS + 255) / 256, 256>>>();
    bin_count<<<NPOINTS_TOTAL / 256, 256>>>(pos);
    bin_scan<<<BATCH, 1024>>>();
    bin_scatter<<<NPOINTS_TOTAL / 256, 256>>>(pos);
    knn_kernel<<<2048, 256>>>(pos);
    proj_kernel<<<1024, 1024, sizeof(ProjSmem)>>>(x, Wq, Wk, Wv);
    attn_kernel<<<NPOINTS_TOTAL / PPB, 256, sizeof(AttnSmem)>>>(
        x, pos, P1, pb1, P2, pb2, A1, ab1, A2, ab2, Wf, bf, out);
}

// round 15
// speedup vs baseline: 1.6628x; 1.0584x over previous
#include <cuda_runtime.h>
#include <cuda_bf16.h>
#include <cstddef>
#include <cstdint>

#define BATCH 2
#define NPTS  8192
#define DIM   64
#define KNN   16
#define NPOINTS_TOTAL (BATCH * NPTS)
#define PPB   8    // points per attn block (128 rows)

#define GRID_RES 16
#define NCELLS   (GRID_RES * GRID_RES * GRID_RES)   // 4096
#define CELL_H   (1.0f / GRID_RES)
#define CAP      640   // per-warp candidate buffer (ints)

// tf32 operand rounding for the K=64 GEMMs (cublas tf32 path emulation).
__device__ __forceinline__ float tf32r(float x) {
    uint32_t y;
    asm("cvt.rna.tf32.f32 %0, %1;" : "=r"(y) : "f"(x));
    return __uint_as_float(y);
}

// ---- packed fp32x2 helpers (Blackwell dual-fp32 pipe) ----
__device__ __forceinline__ unsigned long long pk2(float lo, float hi) {
    unsigned long long r;
    asm("mov.b64 %0, {%1, %2};" : "=l"(r) : "f"(lo), "f"(hi));
    return r;
}
__device__ __forceinline__ unsigned long long splat2(float v) {
    unsigned long long r;
    asm("mov.b64 %0, {%1, %1};" : "=l"(r) : "f"(v));
    return r;
}
__device__ __forceinline__ void fma2(unsigned long long& d,
                                     unsigned long long a, unsigned long long b) {
    asm("fma.rn.f32x2 %0, %1, %2, %0;" : "+l"(d) : "l"(a), "l"(b));
}
__device__ __forceinline__ void unpk2(unsigned long long v, float& lo, float& hi) {
    asm("mov.b64 {%0, %1}, %2;" : "=f"(lo), "=f"(hi) : "l"(v));
}

// ---------------- scratch (static device globals; no runtime allocation) ----
__device__ float g_xq[NPOINTS_TOTAL * DIM];
__device__ float g_xk[NPOINTS_TOTAL * DIM];
__device__ float g_xv[NPOINTS_TOTAL * DIM];
__device__ int   g_idx[NPOINTS_TOTAL * KNN];

__device__ int    g_cellcnt[BATCH * NCELLS];
__device__ int    g_cellstart[BATCH * NCELLS];
__device__ int    g_cursor[BATCH * NCELLS];
__device__ float4 g_bpos[BATCH * NPTS];
__device__ int    g_bidx[BATCH * NPTS];

__device__ __forceinline__ int cell_of(float x, float y, float z) {
    int cx = (int)(x * GRID_RES); cx = cx < 0 ? 0 : (cx > GRID_RES - 1 ? GRID_RES - 1 : cx);
    int cy = (int)(y * GRID_RES); cy = cy < 0 ? 0 : (cy > GRID_RES - 1 ? GRID_RES - 1 : cy);
    int cz = (int)(z * GRID_RES); cz = cz < 0 ? 0 : (cz > GRID_RES - 1 ? GRID_RES - 1 : cz);
    return (cz * GRID_RES + cy) * GRID_RES + cx;
}

// ---- binning kernels (unchanged from passing R14) ----
__global__ void bin_zero() {
    const int i = blockIdx.x * 256 + threadIdx.x;
    if (i < BATCH * NCELLS) g_cellcnt[i] = 0;
}

__global__ void bin_count(const float* __restrict__ pos) {
    const int i = blockIdx.x * 256 + threadIdx.x;
    const float x = pos[i * 3 + 0];
    const float y = pos[i * 3 + 1];
    const float z = pos[i * 3 + 2];
    const int b = i >> 13;
    atomicAdd(&g_cellcnt[b * NCELLS + cell_of(x, y, z)], 1);
}

__global__ void bin_scan() {
    __shared__ int sc[1024];
    const int b = blockIdx.x;
    const int t = threadIdx.x;
    const int base = b * NCELLS + t * 4;
    const int c0 = g_cellcnt[base + 0];
    const int c1 = g_cellcnt[base + 1];
    const int c2 = g_cellcnt[base + 2];
    const int c3 = g_cellcnt[base + 3];
    const int own = c0 + c1 + c2 + c3;
    sc[t] = own;
    __syncthreads();
    int incl = own;
    for (int off = 1; off < 1024; off <<= 1) {
        const int u = (t >= off) ? sc[t - off] : 0;
        __syncthreads();
        incl += u;
        sc[t] = incl;
        __syncthreads();
    }
    const int excl = incl - own;
    const int gb = b * NPTS;
    g_cellstart[base + 0] = gb + excl;
    g_cellstart[base + 1] = gb + excl + c0;
    g_cellstart[base + 2] = gb + excl + c0 + c1;
    g_cellstart[base + 3] = gb + excl + c0 + c1 + c2;
    g_cursor[base + 0] = gb + excl;
    g_cursor[base + 1] = gb + excl + c0;
    g_cursor[base + 2] = gb + excl + c0 + c1;
    g_cursor[base + 3] = gb + excl + c0 + c1 + c2;
}

__global__ void bin_scatter(const float* __restrict__ pos) {
    const int i = blockIdx.x * 256 + threadIdx.x;
    const float x = pos[i * 3 + 0];
    const float y = pos[i * 3 + 1];
    const float z = pos[i * 3 + 2];
    const float sq = __fadd_rn(__fadd_rn(__fmul_rn(x, x), __fmul_rn(y, y)),
                               __fmul_rn(z, z));
    const int b = i >> 13;
    const int slot = atomicAdd(&g_cursor[b * NCELLS + cell_of(x, y, z)], 1);
    g_bpos[slot] = make_float4(x, y, z, sq);
    g_bidx[slot] = i & (NPTS - 1);
}

// ============================================================================
// KNN search v2: start at R=1 with an exact PER-QUERY completeness bound
// (min face gap to unexamined half-spaces) instead of the worst-case (R*h).
// Most queries finish after the 27-cell cube (~54 candidates). Distance
// formula and (d2, idx) insert machinery bit-identical to passing R14.
// ============================================================================
__global__ void __launch_bounds__(256) knn_kernel(const float* __restrict__ pos) {
    const int b    = blockIdx.x >> 10;
    const int blk  = blockIdx.x & 1023;
    const int w    = threadIdx.x >> 5;
    const int lane = threadIdx.x & 31;
    const int n    = blk * 8 + w;
    const unsigned FULL = 0xffffffffu;

    const float qx = pos[((size_t)b * NPTS + n) * 3 + 0];
    const float qy = pos[((size_t)b * NPTS + n) * 3 + 1];
    const float qz = pos[((size_t)b * NPTS + n) * 3 + 2];
    const float sqq = __fadd_rn(__fadd_rn(__fmul_rn(qx, qx), __fmul_rn(qy, qy)),
                                __fmul_rn(qz, qz));

    int cqx = (int)(qx * GRID_RES); cqx = cqx < 0 ? 0 : (cqx > 15 ? 15 : cqx);
    int cqy = (int)(qy * GRID_RES); cqy = cqy < 0 ? 0 : (cqy > 15 ? 15 : cqy);
    int cqz = (int)(qz * GRID_RES); cqz = cqz < 0 ? 0 : (cqz > 15 ? 15 : cqz);

    __shared__ int buf[8][CAP];

    float kd = 1e30f;
    int   ki = 0x7fffffff;
    float thr   = 1e30f;
    int   thrid = 0x7fffffff;

    const int cbase = b * NCELLS;

    for (int R = 1; ; R++) {
        const int side = 2 * R + 1;
        const int ncc  = side * side * side;
        for (int cb = 0; cb < ncc; cb += 32) {
            const int ci = cb + lane;
            int cnt = 0, start = 0;
            if (ci < ncc) {
                const int dz0 = ci / (side * side);
                const int rem = ci - dz0 * side * side;
                const int dy0 = rem / side;
                const int dx0 = rem - dy0 * side;
                const int dx = dx0 - R, dy = dy0 - R, dz = dz0 - R;
                const int adx = dx < 0 ? -dx : dx;
                const int ady = dy < 0 ? -dy : dy;
                const int adz = dz < 0 ? -dz : dz;
                const int cheb = adx > ady ? (adx > adz ? adx : adz) : (ady > adz ? ady : adz);
                if (R == 1 || cheb == R) {   // full cube at R=1, ring-only after
                    const int cx = cqx + dx, cy = cqy + dy, cz = cqz + dz;
                    if (cx >= 0 && cx < GRID_RES && cy >= 0 && cy < GRID_RES &&
                        cz >= 0 && cz < GRID_RES) {
                        const int cell = cbase + (cz * GRID_RES + cy) * GRID_RES + cx;
                        cnt   = g_cellcnt[cell];
                        start = g_cellstart[cell];
                    }
                }
            }
            // warp exclusive scan of cnt
            int incl = cnt;
#pragma unroll
            for (int off = 1; off < 32; off <<= 1) {
                const int u = __shfl_up_sync(FULL, incl, off);
                if (lane >= off) incl += u;
            }
            int total = __shfl_sync(FULL, incl, 31);
            const int excl = incl - cnt;
            for (int t2 = 0; t2 < cnt; t2++) {
                const int o = excl + t2;
                if (o < CAP) buf[w][o] = start + t2;
            }
            __syncwarp();
            if (total > CAP) total = CAP;

            for (int bb = 0; bb < total; bb += 32) {
                const int o = bb + lane;
                float d2 = 1e30f;
                int   j  = 0x7fffffff;
                bool qual = false;
                if (o < total) {
                    const int slot = buf[w][o];
                    const float4 p = g_bpos[slot];
                    j = g_bidx[slot];
                    const float dot = __fadd_rn(__fadd_rn(__fmul_rn(qx, p.x),
                                                          __fmul_rn(qy, p.y)),
                                                __fmul_rn(qz, p.z));
                    d2 = __fsub_rn(__fadd_rn(sqq, p.w), __fmul_rn(2.0f, dot));
                    qual = (d2 < thr) || (d2 == thr && j < thrid);
                }
                unsigned mask = __ballot_sync(FULL, qual);
                while (mask) {
                    const int src = __ffs(mask) - 1;
                    mask &= mask - 1;
                    const float nd = __shfl_sync(FULL, d2, src);
                    const int   nj = __shfl_sync(FULL, j, src);
                    if (nd < thr || (nd == thr && nj < thrid)) {
                        const bool less = (kd < nd) || (kd == nd && ki < nj);
                        const unsigned lm = __ballot_sync(FULL, less && (lane < 16));
                        const int pos2 = __popc(lm);
                        const float upkd = __shfl_up_sync(FULL, kd, 1);
                        const int   upki = __shfl_up_sync(FULL, ki, 1);
                        if (lane >= pos2) {
                            if (lane == pos2) { kd = nd; ki = nj; }
                            else              { kd = upkd; ki = upki; }
                        }
                        thr   = __shfl_sync(FULL, kd, 15);
                        thrid = __shfl_sync(FULL, ki, 15);
                    }
                }
            }
            __syncwarp();   // buf reads done before next stage overwrites
        }
        // per-query exact completeness bound: min face gap to unexamined cells
        const float INF = 1e30f;
        const float gxp = (cqx + R + 1 < GRID_RES) ? ((float)(cqx + R + 1) * CELL_H - qx) : INF;
        const float gxm = (cqx - R > 0)            ? (qx - (float)(cqx - R) * CELL_H)     : INF;
        const float gyp = (cqy + R + 1 < GRID_RES) ? ((float)(cqy + R + 1) * CELL_H - qy) : INF;
        const float gym = (cqy - R > 0)            ? (qy - (float)(cqy - R) * CELL_H)     : INF;
        const float gzp = (cqz + R + 1 < GRID_RES) ? ((float)(cqz + R + 1) * CELL_H - qz) : INF;
        const float gzm = (cqz - R > 0)            ? (qz - (float)(cqz - R) * CELL_H)     : INF;
        const float bound = fminf(fminf(fminf(gxp, gxm), fminf(gyp, gym)), fminf(gzp, gzm));
        if (bound >= 1e29f) break;                         // whole grid covered
        if (thr < bound * bound - 1e-5f) break;            // provably complete
        if (R >= GRID_RES) break;
    }

    if (lane < 16) g_idx[((b << 13) + n) * KNN + lane] = ki;
}

// ============================================================================
// Projection kernel (unchanged).
// ============================================================================
struct ProjSmem {
    float WqT[64 * 68];
    float WkT[64 * 68];
    float WvT[64 * 68];
    float xs[16 * 68];
};

__global__ void __launch_bounds__(1024) proj_kernel(const float* __restrict__ x,
                                                    const float* __restrict__ Wq,
                                                    const float* __restrict__ Wk,
                                                    const float* __restrict__ Wv) {
    extern __shared__ __align__(16) unsigned char proj_raw[];
    ProjSmem* S = reinterpret_cast<ProjSmem*>(proj_raw);

    const int tid = threadIdx.x;
    const int r = tid >> 6;
    const int d = tid & 63;

    for (int e = tid; e < 4096; e += 1024) {
        const int i = e >> 6, c = e & 63;
        S->WqT[c * 68 + i] = tf32r(Wq[e]);
        S->WkT[c * 68 + i] = tf32r(Wk[e]);
        S->WvT[c * 68 + i] = tf32r(Wv[e]);
    }
    const size_t rowbase = (size_t)blockIdx.x * 16;
    for (int e = tid; e < 16 * 64; e += 1024) {
        const int rr = e >> 6, c = e & 63;
        S->xs[rr * 68 + c] = tf32r(x[(rowbase + rr) * 64 + c]);
    }
    __syncthreads();

    const float4* xv4 = (const float4*)(S->xs + r * 68);
    const float4* wq4 = (const float4*)(S->WqT + d * 68);
    const float4* wk4 = (const float4*)(S->WkT + d * 68);
    const float4* wv4 = (const float4*)(S->WvT + d * 68);
    float aq = 0.f, ak = 0.f, av = 0.f;
#pragma unroll
    for (int i = 0; i < 16; i++) {
        const float4 xv = xv4[i];
        const float4 wq = wq4[i];
        const float4 wk = wk4[i];
        const float4 wv = wv4[i];
        aq = fmaf(wq.x, xv.x, aq); aq = fmaf(wq.y, xv.y, aq);
        aq = fmaf(wq.z, xv.z, aq); aq = fmaf(wq.w, xv.w, aq);
        ak = fmaf(wk.x, xv.x, ak); ak = fmaf(wk.y, xv.y, ak);
        ak = fmaf(wk.z, xv.z, ak); ak = fmaf(wk.w, xv.w, ak);
        av = fmaf(wv.x, xv.x, av); av = fmaf(wv.y, xv.y, av);
        av = fmaf(wv.z, xv.z, av); av = fmaf(wv.w, xv.w, av);
    }
    const size_t o = (rowbase + r) * 64 + d;
    g_xq[o] = aq; g_xk[o] = ak; g_xv[o] = av;
}

// ============================================================================
// Attention kernel v6 (unchanged from passing R13/R14).
// ============================================================================
struct AttnSmem {
    float act[128 * 68];
    float w[4][64 * 68];
    float qs[PPB * 68];
    float agg[PPB * 68];
    float rel[128 * 4];
    float P1s[3 * 64];
    float pb1s[64], pb2s[64], ab1s[64], ab2s[64], bfs[64];
};

__global__ void __launch_bounds__(256, 2) attn_kernel(
    const float* __restrict__ x,
    const float* __restrict__ pos,
    const float* __restrict__ P1,
    const float* __restrict__ pb1,
    const float* __restrict__ P2,
    const float* __restrict__ pb2,
    const float* __restrict__ A1,
    const float* __restrict__ ab1,
    const float* __restrict__ A2,
    const float* __restrict__ ab2,
    const float* __restrict__ Wf,
    const float* __restrict__ bf,
    float* __restrict__ out) {
    extern __shared__ __align__(16) unsigned char attn_raw[];
    AttnSmem* S = reinterpret_cast<AttnSmem*>(attn_raw);

    const int tid = threadIdx.x;
    const int tx  = tid & 15;
    const int ty  = tid >> 4;
    const int n0  = tx * 4;
    const int m0  = ty * 8;
    const int p   = ty >> 1;
    const int pbase = blockIdx.x * PPB;
    const int b   = pbase >> 13;

    for (int e = tid; e < 4096; e += 256) {
        const int k = e >> 6, c = e & 63;
        S->w[0][k * 68 + c] = tf32r(P2[e]);
        S->w[1][k * 68 + c] = tf32r(A1[e]);
        S->w[2][k * 68 + c] = tf32r(A2[e]);
        S->w[3][k * 68 + c] = tf32r(Wf[e]);
    }
    if (tid < 192) S->P1s[tid] = P1[tid];
    if (tid < 64) {
        S->pb1s[tid] = pb1[tid];
        S->pb2s[tid] = pb2[tid];
        S->ab1s[tid] = ab1[tid];
        S->ab2s[tid] = ab2[tid];
        S->bfs[tid]  = bf[tid];
    }
    for (int e = tid; e < PPB * 64; e += 256)
        S->qs[(e >> 6) * 68 + (e & 63)] = g_xq[(size_t)pbase * 64 + e];

    int grow[8];
#pragma unroll
    for (int r = 0; r < 8; r++)
        grow[r] = (b << 13) + g_idx[pbase * KNN + m0 + r];

    for (int e = tid; e < 128 * 3; e += 256) {
        const int m = e / 3, c = e % 3;
        const int pp = m >> 4;
        const int nb = g_idx[pbase * KNN + m];
        S->rel[m * 4 + c] = pos[(size_t)(pbase + pp) * 3 + c]
                          - pos[((size_t)(b << 13) + nb) * 3 + c];
    }
    __syncthreads();

    {
        float4* a4 = (float4*)(S->act);
#pragma unroll
        for (int r = 0; r < 8; r++) {
            const int m = m0 + r;
            const float r0 = S->rel[m * 4 + 0];
            const float r1 = S->rel[m * 4 + 1];
            const float r2 = S->rel[m * 4 + 2];
            float4 hv;
#pragma unroll
            for (int c = 0; c < 4; c++) {
                const int n = n0 + c;
                const float dotp = __fadd_rn(__fadd_rn(__fmul_rn(r0, S->P1s[n]),
                                                       __fmul_rn(r1, S->P1s[64 + n])),
                                             __fmul_rn(r2, S->P1s[128 + n]));
                const float hd = __fadd_rn(dotp, S->pb1s[n]);
                ((float*)&hv)[c] = tf32r(fmaxf(hd, 0.f));
            }
            a4[m * 17 + tx] = hv;
        }
    }
    __syncthreads();

    unsigned long long acc2[8][2];
    float pe[8][4];

#define ACC_INIT(BIAS)                                                        \
    {                                                                         \
        const unsigned long long b01 = pk2((BIAS)[n0 + 0], (BIAS)[n0 + 1]);   \
        const unsigned long long b23 = pk2((BIAS)[n0 + 2], (BIAS)[n0 + 3]);   \
        _Pragma("unroll")                                                     \
        for (int r = 0; r < 8; r++) { acc2[r][0] = b01; acc2[r][1] = b23; }   \
    }

#define GEMM_PHASE(WIDX)                                                      \
    {                                                                         \
        const ulonglong2* wb2 = (const ulonglong2*)(S->w[WIDX]);              \
        const float4* in4 = (const float4*)(S->act);                          \
        _Pragma("unroll 2")                                                   \
        for (int kq = 0; kq < 16; kq++) {                                     \
            const ulonglong2 W0 = wb2[(4 * kq + 0) * 17 + tx];                \
            const ulonglong2 W1 = wb2[(4 * kq + 1) * 17 + tx];                \
            const ulonglong2 W2 = wb2[(4 * kq + 2) * 17 + tx];                \
            const ulonglong2 W3 = wb2[(4 * kq + 3) * 17 + tx];                \
            _Pragma("unroll")                                                 \
            for (int r = 0; r < 8; r++) {                                     \
                const float4 a = in4[(m0 + r) * 17 + kq];                     \
                const unsigned long long ax = splat2(a.x);                    \
                const unsigned long long ay = splat2(a.y);                    \
                const unsigned long long az = splat2(a.z);                    \
                const unsigned long long aw = splat2(a.w);                    \
                fma2(acc2[r][0], ax, W0.x); fma2(acc2[r][1], ax, W0.y);       \
                fma2(acc2[r][0], ay, W1.x); fma2(acc2[r][1], ay, W1.y);       \
                fma2(acc2[r][0], az, W2.x); fma2(acc2[r][1], az, W2.y);       \
                fma2(acc2[r][0], aw, W3.x); fma2(acc2[r][1], aw, W3.y);       \
            }                                                                 \
        }                                                                     \
    }

    ACC_INIT(S->pb2s);
    GEMM_PHASE(0);
    __syncthreads();
    {
        const float4 qv = ((const float4*)(S->qs))[p * 17 + tx];
        float4* a4 = (float4*)(S->act);
#pragma unroll
        for (int r = 0; r < 8; r++) {
            unpk2(acc2[r][0], pe[r][0], pe[r][1]);
            unpk2(acc2[r][1], pe[r][2], pe[r][3]);
            const float4 kv = *(const float4*)(g_xk + (size_t)grow[r] * 64 + n0);
            float4 hv;
            hv.x = tf32r(qv.x - kv.x + pe[r][0]);
            hv.y = tf32r(qv.y - kv.y + pe[r][1]);
            hv.z = tf32r(qv.z - kv.z + pe[r][2]);
            hv.w = tf32r(qv.w - kv.w + pe[r][3]);
            a4[(m0 + r) * 17 + tx] = hv;
        }
    }
    __syncthreads();

    ACC_INIT(S->ab1s);
    GEMM_PHASE(1);
    __syncthreads();
    {
        float4* a4 = (float4*)(S->act);
#pragma unroll
        for (int r = 0; r < 8; r++) {
            float t0, t1, t2, t3;
            unpk2(acc2[r][0], t0, t1);
            unpk2(acc2[r][1], t2, t3);
            float4 tv;
            tv.x = tf32r(fmaxf(t0, 0.f));
            tv.y = tf32r(fmaxf(t1, 0.f));
            tv.z = tf32r(fmaxf(t2, 0.f));
            tv.w = tf32r(fmaxf(t3, 0.f));
            a4[(m0 + r) * 17 + tx] = tv;
        }
    }
    __syncthreads();

    ACC_INIT(S->ab2s);
    GEMM_PHASE(2);
    {
        float acc[8][4];
#pragma unroll
        for (int r = 0; r < 8; r++) {
            unpk2(acc2[r][0], acc[r][0], acc[r][1]);
            unpk2(acc2[r][1], acc[r][2], acc[r][3]);
        }
        float ev[8][4];
#pragma unroll
        for (int c = 0; c < 4; c++) {
            float m = acc[0][c];
#pragma unroll
            for (int r = 1; r < 8; r++) m = fmaxf(m, acc[r][c]);
            const float om = __shfl_xor_sync(0xffffffffu, m, 16);
            m = fmaxf(m, om);
            float s = 0.f;
#pragma unroll
            for (int r = 0; r < 8; r++) {
                ev[r][c] = __expf((acc[r][c] - m) * 0.125f);
                s += ev[r][c];
            }
            s += __shfl_xor_sync(0xffffffffu, s, 16);
#pragma unroll
            for (int r = 0; r < 8; r++) ev[r][c] /= s;
        }
        float ag[4] = {0.f, 0.f, 0.f, 0.f};
#pragma unroll
        for (int r = 0; r < 8; r++) {
            const float4 vv = *(const float4*)(g_xv + (size_t)grow[r] * 64 + n0);
            ag[0] += ev[r][0] * (vv.x + pe[r][0]);
            ag[1] += ev[r][1] * (vv.y + pe[r][1]);
            ag[2] += ev[r][2] * (vv.z + pe[r][2]);
            ag[3] += ev[r][3] * (vv.w + pe[r][3]);
        }
#pragma unroll
        for (int c = 0; c < 4; c++)
            ag[c] += __shfl_xor_sync(0xffffffffu, ag[c], 16);
        if ((ty & 1) == 0) {
            float4 av;
            av.x = tf32r(ag[0]); av.y = tf32r(ag[1]);
            av.z = tf32r(ag[2]); av.w = tf32r(ag[3]);
            ((float4*)(S->agg))[p * 17 + tx] = av;
        }
    }
    __syncthreads();

#pragma unroll
    for (int t2 = 0; t2 < 2; t2++) {
        const int oi = tid + 256 * t2;
        const int pp = oi >> 6;
        const int n  = oi & 63;
        float o = S->bfs[n] + x[(size_t)(pbase + pp) * 64 + n];
        const float* ar = S->agg + pp * 68;
        const float* wf = S->w[3];
#pragma unroll
        for (int k = 0; k < 64; k++)
            o = fmaf(ar[k], wf[k * 68 + n], o);
        out[(size_t)(pbase + pp) * 64 + n] = o;
    }
#undef GEMM_PHASE
#undef ACC_INIT
}

// ============================================================================
// launch
// ============================================================================
extern "C" void kernel_launch(void* const* d_in, const int* in_sizes, int n_in,
                              void* d_out, int out_size) {
    const float* x   = (const float*)d_in[0];
    const float* pos = (const float*)d_in[1];
    const float* Wq  = (const float*)d_in[2];
    const float* Wk  = (const float*)d_in[3];
    const float* Wv  = (const float*)d_in[4];
    const float* P1  = (const float*)d_in[5];
    const float* pb1 = (const float*)d_in[6];
    const float* P2  = (const float*)d_in[7];
    const float* pb2 = (const float*)d_in[8];
    const float* A1  = (const float*)d_in[9];
    const float* ab1 = (const float*)d_in[10];
    const float* A2  = (const float*)d_in[11];
    const float* ab2 = (const float*)d_in[12];
    const float* Wf  = (const float*)d_in[13];
    const float* bf  = (const float*)d_in[14];
    float* out = (float*)d_out;

    cudaFuncSetAttribute(proj_kernel, cudaFuncAttributeMaxDynamicSharedMemorySize,
                         (int)sizeof(ProjSmem));
    cudaFuncSetAttribute(attn_kernel, cudaFuncAttributeMaxDynamicSharedMemorySize,
                         (int)sizeof(AttnSmem));

    bin_zero<<<(BATCH * NCELLS + 255) / 256, 256>>>();
    bin_count<<<NPOINTS_TOTAL / 256, 256>>>(pos);
    bin_scan<<<BATCH, 1024>>>();
    bin_scatter<<<NPOINTS_TOTAL / 256, 256>>>(pos);
    knn_kernel<<<2048, 256>>>(pos);
    proj_kernel<<<1024, 1024, sizeof(ProjSmem)>>>(x, Wq, Wk, Wv);
    attn_kernel<<<NPOINTS_TOTAL / PPB, 256, sizeof(AttnSmem)>>>(
        x, pos, P1, pb1, P2, pb2, A1, ab1, A2, ab2, Wf, bf, out);
}